// round 5
// baseline (speedup 1.0000x reference)
#include <cuda_runtime.h>
#include <cuda_bf16.h>
#include <mma.h>

using namespace nvcuda;

#define T_   512
#define B_   128
#define D_   512
#define H_   1024
#define G3H  3072

// ---- gi_gemm tiling (proven, verbatim) ----
#define MT   128
#define NT   64
#define KT   32
#define PADA 40
#define PADB 72

// ---- persistent scan tiling (proven geometry) ----
#define NCTA    128
#define NCOLS   8       // hidden cols per CTA (x3 gates = 24 packed + 8 pad)
#define NPACK   32
#define WH_LD   40
#define SKT     32
#define SA_LD   40
#define GH_LD   36
#define NCHUNK  (H_ / SKT)   // 32
#define STAGE_ELEMS (2 * B_ * SA_LD)   // hi+lo planes per buffer

__device__ __align__(256) float         g_Gi[(long long)T_ * B_ * G3H];
__device__ __align__(256) __nv_bfloat16 g_hh[2][B_ * H_];
__device__ __align__(256) __nv_bfloat16 g_hl[2][B_ * H_];
__device__ int      g_reset_mode;
__device__ __align__(128) unsigned g_arrive[NCTA * 32];  // flags 128B apart
__device__ unsigned g_epoch;

// ---------------------------------------------------------------------------
__global__ void init_kernel(const unsigned char* __restrict__ resets) {
    const unsigned int* w = (const unsigned int*)resets;
    bool i32 = true, f32 = true;
    for (int i = 0; i < 16; i++) {
        unsigned int v = w[i];
        if (v != 0u && v != 1u) i32 = false;
        if (v != 0u && v != 0x3F800000u) f32 = false;
    }
    g_reset_mode = i32 ? 1 : (f32 ? 2 : 0);
    g_epoch = 0u;
    for (int i = 0; i < NCTA; i++) g_arrive[i * 32] = 0u;
}

__device__ __forceinline__ bool get_reset(const void* r, int idx) {
    int m = g_reset_mode;
    if (m == 1) return ((const int*)r)[idx] != 0;
    if (m == 2) return ((const float*)r)[idx] != 0.0f;
    return ((const unsigned char*)r)[idx] != 0;
}

__device__ __forceinline__ void split2(float v, __nv_bfloat16& hi, __nv_bfloat16& lo) {
    hi = __float2bfloat16(v);
    lo = __float2bfloat16(v - __bfloat162float(hi));
}

__device__ __forceinline__ void cp16(void* smem, const void* gmem) {
    unsigned s = (unsigned)__cvta_generic_to_shared(smem);
    asm volatile("cp.async.cg.shared.global [%0], [%1], 16;" :: "r"(s), "l"(gmem));
}

__device__ __forceinline__ void st_release(unsigned* p, unsigned v) {
    asm volatile("st.release.gpu.u32 [%0], %1;" :: "l"(p), "r"(v) : "memory");
}
__device__ __forceinline__ unsigned ld_acquire(const unsigned* p) {
    unsigned v;
    asm volatile("ld.acquire.gpu.u32 %0, [%1];" : "=r"(v) : "l"(p) : "memory");
    return v;
}

__global__ void prep_h_kernel(const float* __restrict__ h0,
                              const void* __restrict__ resets)
{
    int i = blockIdx.x * 256 + threadIdx.x;
    int b = i >> 10;
    float v = get_reset(resets, b) ? 0.0f : h0[i];
    __nv_bfloat16 h, l; split2(v, h, l);
    g_hh[0][i] = h;
    g_hl[0][i] = l;
}

// ---------------------------------------------------------------------------
// Phase B: Gi = X @ Wi + bi  (proven, verbatim)
// ---------------------------------------------------------------------------
__global__ __launch_bounds__(256) void gi_gemm_kernel(
    const float* __restrict__ X,
    const float* __restrict__ Wi,
    const float* __restrict__ bi)
{
    __shared__ __align__(16) __nv_bfloat16 sAh[MT * PADA], sAl[MT * PADA];
    __shared__ __align__(16) __nv_bfloat16 sBh[KT * PADB], sBl[KT * PADB];
    __shared__ __align__(16) float sBias[16 * NT];

    const int n0  = blockIdx.x * NT;
    const long long m0 = (long long)blockIdx.y * MT;
    const int tid  = threadIdx.x;
    const int warp = tid >> 5;
    const int wm   = warp & 3;
    const int wn   = warp >> 2;

    for (int i = tid; i < 16 * NT; i += 256) sBias[i] = bi[n0 + (i % NT)];
    __syncthreads();

    wmma::fragment<wmma::accumulator, 16, 16, 16, float> acc[2][2];
    for (int i = 0; i < 2; i++)
        for (int j = 0; j < 2; j++)
            wmma::load_matrix_sync(acc[i][j], &sBias[wn * 32 + j * 16], NT,
                                   wmma::mem_row_major);

    for (int k0 = 0; k0 < D_; k0 += KT) {
        __syncthreads();
        for (int i = tid; i < MT * KT / 4; i += 256) {
            int r = i >> 3;
            int c = (i & 7) * 4;
            float4 v = *(const float4*)(X + (m0 + r) * D_ + k0 + c);
            float vs[4] = {v.x, v.y, v.z, v.w};
            #pragma unroll
            for (int q = 0; q < 4; q++) {
                __nv_bfloat16 h, l; split2(vs[q], h, l);
                sAh[r * PADA + c + q] = h;
                sAl[r * PADA + c + q] = l;
            }
        }
        for (int i = tid; i < KT * NT / 4; i += 256) {
            int r = i >> 4;
            int c = (i & 15) * 4;
            float4 v = *(const float4*)(Wi + (long long)(k0 + r) * G3H + n0 + c);
            float vs[4] = {v.x, v.y, v.z, v.w};
            #pragma unroll
            for (int q = 0; q < 4; q++) {
                __nv_bfloat16 h, l; split2(vs[q], h, l);
                sBh[r * PADB + c + q] = h;
                sBl[r * PADB + c + q] = l;
            }
        }
        __syncthreads();

        #pragma unroll
        for (int kk = 0; kk < KT; kk += 16) {
            wmma::fragment<wmma::matrix_a, 16, 16, 16, __nv_bfloat16, wmma::row_major> ah[2], al[2];
            wmma::fragment<wmma::matrix_b, 16, 16, 16, __nv_bfloat16, wmma::row_major> bh[2], bl[2];
            #pragma unroll
            for (int i = 0; i < 2; i++) {
                wmma::load_matrix_sync(ah[i], &sAh[(wm * 32 + i * 16) * PADA + kk], PADA);
                wmma::load_matrix_sync(al[i], &sAl[(wm * 32 + i * 16) * PADA + kk], PADA);
            }
            #pragma unroll
            for (int j = 0; j < 2; j++) {
                wmma::load_matrix_sync(bh[j], &sBh[kk * PADB + wn * 32 + j * 16], PADB);
                wmma::load_matrix_sync(bl[j], &sBl[kk * PADB + wn * 32 + j * 16], PADB);
            }
            #pragma unroll
            for (int i = 0; i < 2; i++)
                #pragma unroll
                for (int j = 0; j < 2; j++) {
                    wmma::mma_sync(acc[i][j], al[i], bh[j], acc[i][j]);
                    wmma::mma_sync(acc[i][j], ah[i], bl[j], acc[i][j]);
                    wmma::mma_sync(acc[i][j], ah[i], bh[j], acc[i][j]);
                }
        }
    }

    for (int i = 0; i < 2; i++)
        for (int j = 0; j < 2; j++) {
            float* p = g_Gi + (m0 + wm * 32 + i * 16) * G3H + n0 + wn * 32 + j * 16;
            wmma::store_matrix_sync(p, acc[i][j], G3H, wmma::mem_row_major);
        }
}

// ---------------------------------------------------------------------------
// Persistent scan: 128 CTAs x 512 threads. 3-stage cp.async pipeline,
// one __syncthreads per chunk, flag-tree grid barrier, register prefetch.
// ---------------------------------------------------------------------------
__global__ __launch_bounds__(512, 1) void scan_kernel(
    const float* __restrict__ Wh,
    const float* __restrict__ bhn,
    const void*  __restrict__ resets,
    float*       __restrict__ out)
{
    extern __shared__ __align__(16) char sm[];
    __nv_bfloat16* sWh = (__nv_bfloat16*)sm;             // [1024][40]
    __nv_bfloat16* sWl = sWh + H_ * WH_LD;               // [1024][40]
    __nv_bfloat16* sStage = sWl + H_ * WH_LD;            // 3 bufs x (hi+lo) x [128][40]
    float* sGh = (float*)sStage;                         // alias (epilogue; fits in buf0)
    __shared__ unsigned char sRstN[B_];

    const int tid  = threadIdx.x;
    const int warp = tid >> 5;
    const int wm   = warp & 7;
    const int wn   = warp >> 3;
    const int bid  = blockIdx.x;
    const int j0   = bid * NCOLS;

    // preload packed Wh slice (proven layout)
    for (int idx = tid; idx < H_ * NPACK; idx += 512) {
        int k = idx >> 5;
        int c = idx & 31;
        float v = 0.0f;
        if (c < 24) v = Wh[(long long)k * G3H + (c >> 3) * H_ + j0 + (c & 7)];
        __nv_bfloat16 h, l; split2(v, h, l);
        sWh[k * WH_LD + c] = h;
        sWl[k * WH_LD + c] = l;
    }
    float lbhn[NCOLS];
    #pragma unroll
    for (int c = 0; c < NCOLS; c++) lbhn[c] = bhn[j0 + c];

    // epilogue element indices (fixed per thread)
    const int b0_  = tid >> 3,           cj0 = tid & 7;
    const int b1_  = (tid + 512) >> 3,   cj1 = (tid + 512) & 7;
    const int hidx0 = b0_ * H_ + j0 + cj0;
    const int hidx1 = b1_ * H_ + j0 + cj1;

    __syncthreads();

    for (int t = 0; t < T_; t++) {
        const __nv_bfloat16* hsh = g_hh[t & 1];
        const __nv_bfloat16* hsl = g_hl[t & 1];

        if (tid < B_)
            sRstN[tid] = (t + 1 < T_) ? (get_reset(resets, (t + 1) * B_ + tid) ? 1 : 0) : 0;

        auto stage = [&](int kc, int buf) {
            __nv_bfloat16* sh = sStage + buf * STAGE_ELEMS;
            __nv_bfloat16* sl = sh + B_ * SA_LD;
            const int k0 = kc * SKT;
            int r = tid >> 2;
            int c = (tid & 3) * 8;
            cp16(&sh[r * SA_LD + c], &hsh[r * H_ + k0 + c]);
            cp16(&sl[r * SA_LD + c], &hsl[r * H_ + k0 + c]);
        };

        wmma::fragment<wmma::accumulator, 16, 16, 16, float> acc;
        wmma::fill_fragment(acc, 0.0f);

        stage(0, 0);
        asm volatile("cp.async.commit_group;");
        stage(1, 1);
        asm volatile("cp.async.commit_group;");

        // register prefetch: gi (DRAM, streaming) + hp (self-owned, L2/L1 hot)
        const float* gi_base = g_Gi + (long long)t * B_ * G3H;
        float ir0 = __ldcs(gi_base + (long long)b0_ * G3H + j0 + cj0);
        float iz0 = __ldcs(gi_base + (long long)b0_ * G3H + H_ + j0 + cj0);
        float in0 = __ldcs(gi_base + (long long)b0_ * G3H + 2 * H_ + j0 + cj0);
        float ir1 = __ldcs(gi_base + (long long)b1_ * G3H + j0 + cj1);
        float iz1 = __ldcs(gi_base + (long long)b1_ * G3H + H_ + j0 + cj1);
        float in1 = __ldcs(gi_base + (long long)b1_ * G3H + 2 * H_ + j0 + cj1);
        float hp0 = __bfloat162float(hsh[hidx0]) + __bfloat162float(hsl[hidx0]);
        float hp1 = __bfloat162float(hsh[hidx1]) + __bfloat162float(hsl[hidx1]);

        for (int kc = 0; kc < NCHUNK; kc++) {
            const int buf = kc - (kc / 3) * 3;   // kc % 3
            if (kc + 1 < NCHUNK) asm volatile("cp.async.wait_group 1;");
            else                 asm volatile("cp.async.wait_group 0;");
            __syncthreads();
            if (kc + 2 < NCHUNK) {
                int nb = kc + 2;
                stage(nb, nb - (nb / 3) * 3);
                asm volatile("cp.async.commit_group;");
            }

            const __nv_bfloat16* sh = sStage + buf * STAGE_ELEMS;
            const __nv_bfloat16* sl = sh + B_ * SA_LD;
            #pragma unroll
            for (int kk = 0; kk < SKT; kk += 16) {
                wmma::fragment<wmma::matrix_a, 16, 16, 16, __nv_bfloat16, wmma::row_major> ah, al;
                wmma::fragment<wmma::matrix_b, 16, 16, 16, __nv_bfloat16, wmma::row_major> bh, bl;
                wmma::load_matrix_sync(ah, &sh[(wm * 16) * SA_LD + kk], SA_LD);
                wmma::load_matrix_sync(al, &sl[(wm * 16) * SA_LD + kk], SA_LD);
                int kg = kc * SKT + kk;
                wmma::load_matrix_sync(bh, &sWh[kg * WH_LD + wn * 16], WH_LD);
                wmma::load_matrix_sync(bl, &sWl[kg * WH_LD + wn * 16], WH_LD);
                wmma::mma_sync(acc, al, bh, acc);
                wmma::mma_sync(acc, ah, bl, acc);
                wmma::mma_sync(acc, ah, bh, acc);
            }
        }

        // epilogue: sGh aliases stage buffer 0 (last compute used buf 1)
        __syncthreads();
        wmma::store_matrix_sync(&sGh[(wm * 16) * GH_LD + wn * 16], acc, GH_LD,
                                wmma::mem_row_major);
        __syncthreads();

        float* out_t = out + (long long)t * B_ * H_;
        {
            float ghr = sGh[b0_ * GH_LD + cj0];
            float ghz = sGh[b0_ * GH_LD + 8 + cj0];
            float ghn = sGh[b0_ * GH_LD + 16 + cj0];
            float r = 1.f / (1.f + __expf(-(ir0 + ghr)));
            float z = 1.f / (1.f + __expf(-(iz0 + ghz)));
            float n = tanhf(in0 + r * (ghn + lbhn[cj0]));
            float hnew = (1.f - z) * n + z * hp0;
            out_t[hidx0] = hnew;
            if (t + 1 < T_) {
                float m = sRstN[b0_] ? 0.f : hnew;
                __nv_bfloat16 h, l; split2(m, h, l);
                g_hh[(t + 1) & 1][hidx0] = h;
                g_hl[(t + 1) & 1][hidx0] = l;
            }
        }
        {
            float ghr = sGh[b1_ * GH_LD + cj1];
            float ghz = sGh[b1_ * GH_LD + 8 + cj1];
            float ghn = sGh[b1_ * GH_LD + 16 + cj1];
            float r = 1.f / (1.f + __expf(-(ir1 + ghr)));
            float z = 1.f / (1.f + __expf(-(iz1 + ghz)));
            float n = tanhf(in1 + r * (ghn + lbhn[cj1]));
            float hnew = (1.f - z) * n + z * hp1;
            out_t[hidx1] = hnew;
            if (t + 1 < T_) {
                float m = sRstN[b1_] ? 0.f : hnew;
                __nv_bfloat16 h, l; split2(m, h, l);
                g_hh[(t + 1) & 1][hidx1] = h;
                g_hl[(t + 1) & 1][hidx1] = l;
            }
        }

        // flag-tree grid barrier (monotonic epoch t+1)
        __threadfence();
        __syncthreads();
        const unsigned target = (unsigned)(t + 1);
        if (tid == 0) st_release(&g_arrive[bid * 32], target);
        if (bid == 0) {
            if (tid < NCTA) {
                while (ld_acquire(&g_arrive[tid * 32]) < target) __nanosleep(20);
            }
            __syncthreads();
            if (tid == 0) st_release(&g_epoch, target);
        }
        if (tid == 0) {
            while (ld_acquire(&g_epoch) < target) __nanosleep(20);
        }
        __syncthreads();
    }
}

// ---------------------------------------------------------------------------
extern "C" void kernel_launch(void* const* d_in, const int* in_sizes, int n_in,
                              void* d_out, int out_size)
{
    const float* x      = (const float*)d_in[0];
    const void*  resets = d_in[1];
    const float* h0     = (const float*)d_in[2];
    const float* Wi     = (const float*)d_in[3];
    const float* bi     = (const float*)d_in[4];
    const float* Wh     = (const float*)d_in[5];
    const float* bhn    = (const float*)d_in[6];
    float* out = (float*)d_out;

    // dynamic smem: Wh hi/lo [1024][40] + 3-buf stage (hi+lo) [128][40]
    const size_t scan_smem = (size_t)(2 * H_ * WH_LD + 3 * STAGE_ELEMS) * sizeof(__nv_bfloat16);
    cudaFuncSetAttribute(scan_kernel, cudaFuncAttributeMaxDynamicSharedMemorySize,
                         (int)scan_smem);

    init_kernel<<<1, 1>>>((const unsigned char*)resets);
    prep_h_kernel<<<(B_ * H_) / 256, 256>>>(h0, resets);
    gi_gemm_kernel<<<dim3(G3H / NT, (T_ * B_) / MT), 256>>>(x, Wi, bi);
    scan_kernel<<<NCTA, 512, scan_smem>>>(Wh, bhn, resets, out);
}